// round 7
// baseline (speedup 1.0000x reference)
#include <cuda_runtime.h>
#include <cuda_bf16.h>
#include <cstdint>

typedef unsigned int u32; typedef unsigned long long u64; typedef unsigned short u16;

#define NQ 32768
#define SGRID 32768
#define NEDGE 262144
#define C 192
#define C2 384
#define IDXMASK 32767
// fp32 helper-kernel geometry
#define TILE 64
#define NTHR 384
#define KT 32
#define SROW 66
// mma edge kernel geometry
#define TM 64
#define ETHR 256
// smem offsets (bytes) for k_edges_mma
#define AH0O 0
#define AL0O 50176
#define AH1O 100352
#define AL1O 150528
#define WHO  200704
#define WLO  215040
#define QSO  229376
#define SMEM_E 229632

__device__ __align__(16) float g_xf[(size_t)SGRID * C];
__device__ __align__(16) float g_qe[(size_t)NQ * C];
__device__ __align__(16) float g_seg[(size_t)NQ * C];
__device__ int g_cnt[NQ];
__device__ int g_edge64;
// W^T split hi/lo: L0 [384][384]@0, L1 @147456, L2 padded [256][384]@294912
__device__ __align__(16) __nv_bfloat16 g_wth[393216];
__device__ __align__(16) __nv_bfloat16 g_wtl[393216];

// ---------- helpers ----------
__device__ __forceinline__ u32 smem_u32(const void* p) {
    u32 a; asm("{ .reg .u64 t; cvta.to.shared.u64 t, %1; cvt.u32.u64 %0, t; }" : "=r"(a) : "l"(p)); return a;
}
__device__ __forceinline__ float gelu_f(float x) {
    return 0.5f * x * (1.0f + erff(x * 0.7071067811865476f));
}
__device__ __forceinline__ void load_edge(const void* Eg, int e, int& q, int& g) {
    if (g_edge64) {
        const long long* E = (const long long*)Eg;
        q = (int)E[2 * (size_t)e] & IDXMASK; g = (int)E[2 * (size_t)e + 1] & IDXMASK;
    } else {
        const int* E = (const int*)Eg;
        q = E[2 * (size_t)e] & IDXMASK; g = E[2 * (size_t)e + 1] & IDXMASK;
    }
}
__device__ __forceinline__ void split2(float v, u16& h, u16& l) {
    __nv_bfloat16 hb = __float2bfloat16_rn(v);
    h = __bfloat16_as_ushort(hb);
    l = __bfloat16_as_ushort(__float2bfloat16_rn(v - __bfloat162float(hb)));
}
__device__ __forceinline__ void ldsm4(u32* r, u32 addr) {
    asm volatile("ldmatrix.sync.aligned.m8n8.x4.shared.b16 {%0,%1,%2,%3}, [%4];"
        : "=r"(r[0]), "=r"(r[1]), "=r"(r[2]), "=r"(r[3]) : "r"(addr));
}
__device__ __forceinline__ void ldsm2(u32* r, u32 addr) {
    asm volatile("ldmatrix.sync.aligned.m8n8.x2.shared.b16 {%0,%1}, [%2];"
        : "=r"(r[0]), "=r"(r[1]) : "r"(addr));
}
__device__ __forceinline__ void mma16816(float* c, const u32* a, const u32* b) {
    asm volatile("mma.sync.aligned.m16n8k16.row.col.f32.bf16.bf16.f32 "
        "{%0,%1,%2,%3}, {%4,%5,%6,%7}, {%8,%9}, {%0,%1,%2,%3};"
        : "+f"(c[0]), "+f"(c[1]), "+f"(c[2]), "+f"(c[3])
        : "r"(a[0]), "r"(a[1]), "r"(a[2]), "r"(a[3]), "r"(b[0]), "r"(b[1]));
}

// ---------- fp32x2 path (proj / pred) ----------
__device__ __forceinline__ u64 pk2(float lo, float hi) { u64 r; asm("mov.b64 %0,{%1,%2};" : "=l"(r) : "f"(lo), "f"(hi)); return r; }
__device__ __forceinline__ void upk2(u64 v, float& lo, float& hi) { asm("mov.b64 {%0,%1},%2;" : "=f"(lo), "=f"(hi) : "l"(v)); }
__device__ __forceinline__ u64 fma2(u64 a, u64 b, u64 c) { u64 d; asm("fma.rn.f32x2 %0,%1,%2,%3;" : "=l"(d) : "l"(a), "l"(b), "l"(c)); return d; }

template<int KIN, int NTOT, bool DOGELU>
__device__ __forceinline__ void layer_mlp(const float* __restrict__ Wg, const float* __restrict__ bg,
                                          const float* src, float* dst, float* wt, int tid)
{
    const int tx = tid % 48, ty = tid / 48;
    for (int nc = 0; nc < NTOT; nc += 192) {
        u64 acc[4][4];
        #pragma unroll
        for (int p = 0; p < 4; p++)
            #pragma unroll
            for (int ci = 0; ci < 4; ci++) acc[p][ci] = 0ull;
        for (int kt0 = 0; kt0 < KIN; kt0 += KT) {
            #pragma unroll
            for (int j = 0; j < 4; j++) {
                int f = tid + j * NTHR, r = f / 48, c4 = f % 48;
                float4 v = *(const float4*)&Wg[(size_t)(kt0 + r) * NTOT + nc + c4 * 4];
                *(float4*)&wt[r * 192 + c4 * 4] = v;
            }
            __syncthreads();
            #pragma unroll
            for (int kk = 0; kk < KT; kk++) {
                const float* srow = src + (kt0 + kk) * SROW + 8 * ty;
                u64 a0 = *(const u64*)&srow[0], a1 = *(const u64*)&srow[2];
                u64 a2 = *(const u64*)&srow[4], a3 = *(const u64*)&srow[6];
                float4 bv = *(const float4*)&wt[kk * 192 + tx * 4];
                u64 b0 = pk2(bv.x, bv.x), b1 = pk2(bv.y, bv.y), b2 = pk2(bv.z, bv.z), b3 = pk2(bv.w, bv.w);
                acc[0][0]=fma2(a0,b0,acc[0][0]); acc[0][1]=fma2(a0,b1,acc[0][1]); acc[0][2]=fma2(a0,b2,acc[0][2]); acc[0][3]=fma2(a0,b3,acc[0][3]);
                acc[1][0]=fma2(a1,b0,acc[1][0]); acc[1][1]=fma2(a1,b1,acc[1][1]); acc[1][2]=fma2(a1,b2,acc[1][2]); acc[1][3]=fma2(a1,b3,acc[1][3]);
                acc[2][0]=fma2(a2,b0,acc[2][0]); acc[2][1]=fma2(a2,b1,acc[2][1]); acc[2][2]=fma2(a2,b2,acc[2][2]); acc[2][3]=fma2(a2,b3,acc[2][3]);
                acc[3][0]=fma2(a3,b0,acc[3][0]); acc[3][1]=fma2(a3,b1,acc[3][1]); acc[3][2]=fma2(a3,b2,acc[3][2]); acc[3][3]=fma2(a3,b3,acc[3][3]);
            }
            __syncthreads();
        }
        #pragma unroll
        for (int ci = 0; ci < 4; ci++) {
            int col = nc + tx * 4 + ci;
            float bb = bg[col];
            #pragma unroll
            for (int p = 0; p < 4; p++) {
                float lo, hi; upk2(acc[p][ci], lo, hi);
                lo += bb; hi += bb;
                if (DOGELU) { lo = gelu_f(lo); hi = gelu_f(hi); }
                *(u64*)&dst[(size_t)col * SROW + 8 * ty + 2 * p] = pk2(lo, hi);
            }
        }
    }
}

// ---------- small kernels ----------
__global__ void k_detect(const int* __restrict__ E32) {
    if (threadIdx.x == 0) {
        int mode = 1;
        for (int i = 1; i < 128; i += 2) if (E32[i] != 0) { mode = 0; break; }
        g_edge64 = mode;
    }
}

__global__ void k_prepw(const float* __restrict__ w0, const float* __restrict__ w1,
                        const float* __restrict__ w2) {
    int idx = blockIdx.x * blockDim.x + threadIdx.x;
    if (idx >= 393216) return;
    float v;
    if (idx < 147456) {
        int n = idx / 384, k = idx % 384;
        v = w0[(size_t)k * 384 + n];
    } else if (idx < 294912) {
        int r = idx - 147456, n = r / 384, k = r % 384;
        v = w1[(size_t)k * 384 + n];
    } else {
        int r = idx - 294912, n = r / 384, k = r % 384;
        v = (n < 192) ? w2[(size_t)k * 192 + n] : 0.0f;
    }
    u16 h, l; split2(v, h, l);
    g_wth[idx] = __ushort_as_bfloat16(h);
    g_wtl[idx] = __ushort_as_bfloat16(l);
}

__global__ void k_embed(const float* __restrict__ qp) {
    int q = blockIdx.x, t = threadIdx.x;
    int d = t >> 5, j = t & 31;
    float c = qp[q * 3 + d];
    float omega = powf(10000.0f, -(float)(2 * j) / 64.0f);
    float s, co; sincosf(c * omega, &s, &co);
    g_qe[(size_t)q * C + d * 64 + j]      = s;
    g_qe[(size_t)q * C + d * 64 + 32 + j] = co;
}

__global__ void __launch_bounds__(NTHR, 1) k_proj(const float* __restrict__ x,
                                                  const float* __restrict__ W,
                                                  const float* __restrict__ b)
{
    extern __shared__ float sm[];
    float* bufA = sm; float* bufB = bufA + C * SROW; float* wt = bufB + C * SROW;
    int tid = threadIdx.x;
    int r0 = blockIdx.x * TILE;
    {
        int e = tid / 6, t2 = tid % 6;
        const float* src = x + (size_t)(r0 + e) * C + t2 * 32;
        int cbase = t2 * 32;
        #pragma unroll
        for (int i = 0; i < 8; i++) {
            float4 v = *(const float4*)(src + i * 4);
            int c = cbase + i * 4;
            bufA[(c+0)*SROW+e]=v.x; bufA[(c+1)*SROW+e]=v.y; bufA[(c+2)*SROW+e]=v.z; bufA[(c+3)*SROW+e]=v.w;
        }
    }
    __syncthreads();
    layer_mlp<C, C, false>(W, b, bufA, bufB, wt, tid);
    __syncthreads();
    #pragma unroll
    for (int j = 0; j < 32; j++) {
        int f = tid + j * NTHR, e = f / C, c = f % C;
        g_xf[(size_t)(r0 + e) * C + c] = bufB[(size_t)c * SROW + e];
    }
}

__global__ void k_zero() {
    int idx = blockIdx.x * blockDim.x + threadIdx.x;
    int stride = gridDim.x * blockDim.x;
    for (int i = idx; i < NQ * C; i += stride) g_seg[i] = 0.0f;
    for (int i = idx; i < NQ; i += stride) g_cnt[i] = 0;
}

// ---------- bf16x3 mma edge MLP + segment sum ----------
__global__ void __launch_bounds__(ETHR, 1) k_edges_mma(const void* __restrict__ Eg,
    const float* __restrict__ b0, const float* __restrict__ b1, const float* __restrict__ b2)
{
    extern __shared__ char smc[];
    const u32 sbase = smem_u32(smc);
    int tid = threadIdx.x, wid = tid >> 5, lane = tid & 31;
    int wm = wid & 1;      // 2 M-warps (rows wm*32..+31)
    int wn = wid >> 1;     // 4 N-warps (cols wn*32..+31 within 128-chunk)
    int* qs = (int*)(smc + QSO);
    int e0 = blockIdx.x * TM;

    // ---- build A (hi/lo bf16) in buf0: [64 edges][384 k], stride 392 ----
    {
        int e = tid >> 2, part = tid & 3;
        int q, g; load_edge(Eg, e0 + e, q, g);
        if (part == 0) qs[e] = q;
        const float* src = (part < 2) ? (g_xf + (size_t)g * C + part * 96)
                                      : (g_qe + (size_t)q * C + (part - 2) * 96);
        int kb = part * 96;
        #pragma unroll 4
        for (int i = 0; i < 24; i++) {
            float4 v = *(const float4*)(src + i * 4);
            int k = kb + i * 4;
            u16 h0,l0,h1,l1,h2,l2,h3,l3;
            split2(v.x,h0,l0); split2(v.y,h1,l1); split2(v.z,h2,l2); split2(v.w,h3,l3);
            u32 off = ((u32)e * 392u + (u32)k) * 2u;
            *(u64*)(smc + AH0O + off) = (u64)((u32)h0|((u32)h1<<16)) | ((u64)((u32)h2|((u32)h3<<16))<<32);
            *(u64*)(smc + AL0O + off) = (u64)((u32)l0|((u32)l1<<16)) | ((u64)((u32)l2|((u32)l3<<16))<<32);
        }
    }
    __syncthreads();

    const int wbase[3]  = {0, 147456, 294912};
    const int nchn[3]   = {3, 3, 2};
    const u32 inoff[3]  = {AH0O, AH1O, AH0O};
    const u32 outoff[3] = {AH1O, AH0O, 0};
    const float* bgs[3] = {b0, b1, b2};
    float* segbuf = (float*)(smc + AH1O);   // L2 fp32 out: [192 cols][stride 65]

    // per-lane constant address pieces
    const u32 arow = (u32)(lane & 15);
    const u32 acol = ((u32)(lane >> 4)) * 8u;
    const u32 brow = (u32)(lane & 7);
    const u32 bcol = ((u32)((lane >> 3) & 1)) * 8u;

    for (int L = 0; L < 3; L++) {
        const u32 IH = sbase + inoff[L], ILo = IH + 50176;
        char* OH = smc + outoff[L]; char* OL = OH + 50176;
        const __nv_bfloat16* WHg = g_wth + wbase[L];
        const __nv_bfloat16* WLg = g_wtl + wbase[L];
        const float* bg = bgs[L];

        for (int nc = 0; nc < nchn[L]; nc++) {
            int n0 = nc * 128;
            float acc[2][4][4];
            #pragma unroll
            for (int mi = 0; mi < 2; mi++)
                #pragma unroll
                for (int ni = 0; ni < 4; ni++)
                    #pragma unroll
                    for (int r = 0; r < 4; r++) acc[mi][ni][r] = 0.0f;

            uint4 pfh[3], pfl[3];
            // preload k-chunk 0
            #pragma unroll
            for (int j = 0; j < 3; j++) {
                int idx = tid * 3 + j, n = idx / 6, k8 = idx % 6;
                pfh[j] = *(const uint4*)(WHg + (size_t)(n0 + n) * 384 + k8 * 8);
                pfl[j] = *(const uint4*)(WLg + (size_t)(n0 + n) * 384 + k8 * 8);
            }
            #pragma unroll
            for (int j = 0; j < 3; j++) {
                int idx = tid * 3 + j, n = idx / 6, k8 = idx % 6;
                u32 o = ((u32)n * 56u + (u32)k8 * 8u) * 2u;
                *(uint4*)(smc + WHO + o) = pfh[j];
                *(uint4*)(smc + WLO + o) = pfl[j];
            }
            __syncthreads();

            for (int kc = 0; kc < 8; kc++) {
                if (kc < 7) {
                    #pragma unroll
                    for (int j = 0; j < 3; j++) {
                        int idx = tid * 3 + j, n = idx / 6, k8 = idx % 6;
                        pfh[j] = *(const uint4*)(WHg + (size_t)(n0 + n) * 384 + (kc + 1) * 48 + k8 * 8);
                        pfl[j] = *(const uint4*)(WLg + (size_t)(n0 + n) * 384 + (kc + 1) * 48 + k8 * 8);
                    }
                }
                #pragma unroll
                for (int ks = 0; ks < 3; ks++) {
                    int k0 = kc * 48 + ks * 16;
                    u32 aH[2][4], aL[2][4];
                    #pragma unroll
                    for (int mi = 0; mi < 2; mi++) {
                        u32 ro = (u32)(wm * 32 + mi * 16) + arow;
                        u32 aoff = (ro * 392u + (u32)k0 + acol) * 2u;
                        ldsm4(aH[mi], IH + aoff);
                        ldsm4(aL[mi], ILo + aoff);
                    }
                    u32 bH[4][2], bL[4][2];
                    #pragma unroll
                    for (int ni = 0; ni < 4; ni++) {
                        u32 ro = (u32)(wn * 32 + ni * 8) + brow;
                        u32 boff = (ro * 56u + (u32)(ks * 16) + bcol) * 2u;
                        ldsm2(bH[ni], sbase + WHO + boff);
                        ldsm2(bL[ni], sbase + WLO + boff);
                    }
                    #pragma unroll
                    for (int mi = 0; mi < 2; mi++)
                        #pragma unroll
                        for (int ni = 0; ni < 4; ni++) {
                            mma16816(acc[mi][ni], aH[mi], bH[ni]);
                            mma16816(acc[mi][ni], aL[mi], bH[ni]);
                            mma16816(acc[mi][ni], aH[mi], bL[ni]);
                        }
                }
                __syncthreads();
                if (kc < 7) {
                    #pragma unroll
                    for (int j = 0; j < 3; j++) {
                        int idx = tid * 3 + j, n = idx / 6, k8 = idx % 6;
                        u32 o = ((u32)n * 56u + (u32)k8 * 8u) * 2u;
                        *(uint4*)(smc + WHO + o) = pfh[j];
                        *(uint4*)(smc + WLO + o) = pfl[j];
                    }
                    __syncthreads();
                }
            }

            // epilogue for this 128-col chunk
            if (L < 2) {
                #pragma unroll
                for (int mi = 0; mi < 2; mi++) {
                    int r0 = wm * 32 + mi * 16 + (lane >> 2);
                    #pragma unroll
                    for (int ni = 0; ni < 4; ni++) {
                        int c = n0 + wn * 32 + ni * 8 + (lane & 3) * 2;
                        float bb0 = bg[c], bb1 = bg[c + 1];
                        float v0 = gelu_f(acc[mi][ni][0] + bb0);
                        float v1 = gelu_f(acc[mi][ni][1] + bb1);
                        float v2 = gelu_f(acc[mi][ni][2] + bb0);
                        float v3 = gelu_f(acc[mi][ni][3] + bb1);
                        u16 h0,l0,h1,l1,h2,l2,h3,l3;
                        split2(v0,h0,l0); split2(v1,h1,l1);
                        split2(v2,h2,l2); split2(v3,h3,l3);
                        u32 o0 = ((u32)r0 * 392u + (u32)c) * 2u;
                        u32 o1 = ((u32)(r0 + 8) * 392u + (u32)c) * 2u;
                        *(u32*)(OH + o0) = (u32)h0 | ((u32)h1 << 16);
                        *(u32*)(OL + o0) = (u32)l0 | ((u32)l1 << 16);
                        *(u32*)(OH + o1) = (u32)h2 | ((u32)h3 << 16);
                        *(u32*)(OL + o1) = (u32)l2 | ((u32)l3 << 16);
                    }
                }
            } else {
                #pragma unroll
                for (int mi = 0; mi < 2; mi++) {
                    int r0 = wm * 32 + mi * 16 + (lane >> 2);
                    #pragma unroll
                    for (int ni = 0; ni < 4; ni++) {
                        int c = n0 + wn * 32 + ni * 8 + (lane & 3) * 2;
                        if (c < 192) {
                            float bb0 = bg[c], bb1 = bg[c + 1];
                            segbuf[(size_t)c * 65 + r0]           = acc[mi][ni][0] + bb0;
                            segbuf[(size_t)(c + 1) * 65 + r0]     = acc[mi][ni][1] + bb1;
                            segbuf[(size_t)c * 65 + r0 + 8]       = acc[mi][ni][2] + bb0;
                            segbuf[(size_t)(c + 1) * 65 + r0 + 8] = acc[mi][ni][3] + bb1;
                        }
                    }
                }
            }
        }
        __syncthreads();
    }

    // ---- segment-sum over sorted runs ----
    if (tid < C) {
        int c = tid;
        int cur = qs[0];
        float s = segbuf[(size_t)c * 65 + 0];
        for (int e = 1; e < TM; e++) {
            int q = qs[e];
            float v = segbuf[(size_t)c * 65 + e];
            if (q == cur) s += v;
            else { atomicAdd(&g_seg[(size_t)cur * C + c], s); cur = q; s = v; }
        }
        atomicAdd(&g_seg[(size_t)cur * C + c], s);
    } else if (tid == C) {
        int cur = qs[0], n = 1;
        for (int e = 1; e < TM; e++) {
            int q = qs[e];
            if (q == cur) n++;
            else { atomicAdd(&g_cnt[cur], n); cur = q; n = 1; }
        }
        atomicAdd(&g_cnt[cur], n);
    }
}

// ---------- prediction head ----------
__global__ void __launch_bounds__(NTHR, 1) k_pred(const float* __restrict__ Wp0,
                                                  const float* __restrict__ bp0,
                                                  const float* __restrict__ Wp1,
                                                  const float* __restrict__ bp1,
                                                  float* __restrict__ out)
{
    extern __shared__ float sm[];
    float* bufA = sm; float* bufB = bufA + C * SROW; float* wt = bufB + C * SROW;
    int tid = threadIdx.x;
    int q0 = blockIdx.x * TILE;
    {
        int e = tid / 6, t2 = tid % 6;
        int q = q0 + e;
        float inv = 1.0f / fmaxf((float)g_cnt[q], 1.0f);
        const float* src = g_seg + (size_t)q * C + t2 * 32;
        int cbase = t2 * 32;
        #pragma unroll
        for (int i = 0; i < 8; i++) {
            float4 v = *(const float4*)(src + i * 4);
            int c = cbase + i * 4;
            bufA[(c+0)*SROW+e]=v.x*inv; bufA[(c+1)*SROW+e]=v.y*inv; bufA[(c+2)*SROW+e]=v.z*inv; bufA[(c+3)*SROW+e]=v.w*inv;
        }
    }
    __syncthreads();
    layer_mlp<C, C, true>(Wp0, bp0, bufA, bufB, wt, tid);
    __syncthreads();
    if (tid < 256) {
        int q = tid >> 2, o = tid & 3;
        float s = bp1[o];
        #pragma unroll 8
        for (int k = 0; k < C; k++)
            s += bufB[(size_t)k * SROW + q] * Wp1[k * 4 + o];
        out[(size_t)(q0 + q) * 4 + o] = s;
    }
}

extern "C" void kernel_launch(void* const* d_in, const int* in_sizes, int n_in,
                              void* d_out, int out_size)
{
    const float* x      = (const float*)d_in[0];
    const float* qp     = (const float*)d_in[1];
    const void*  E      = d_in[2];
    const float* proj_w = (const float*)d_in[3];
    const float* proj_b = (const float*)d_in[4];
    const float* m0w    = (const float*)d_in[5];
    const float* m0b    = (const float*)d_in[6];
    const float* m1w    = (const float*)d_in[7];
    const float* m1b    = (const float*)d_in[8];
    const float* m2w    = (const float*)d_in[9];
    const float* m2b    = (const float*)d_in[10];
    const float* p0w    = (const float*)d_in[11];
    const float* p0b    = (const float*)d_in[12];
    const float* p1w    = (const float*)d_in[13];
    const float* p1b    = (const float*)d_in[14];
    float* out = (float*)d_out;

    const int SM_SMALL = (2 * C * SROW + KT * 192) * 4;

    cudaFuncSetAttribute(k_edges_mma, cudaFuncAttributeMaxDynamicSharedMemorySize, SMEM_E);
    cudaFuncSetAttribute(k_proj, cudaFuncAttributeMaxDynamicSharedMemorySize, SM_SMALL);
    cudaFuncSetAttribute(k_pred, cudaFuncAttributeMaxDynamicSharedMemorySize, SM_SMALL);

    k_detect<<<1, 32>>>((const int*)E);
    k_prepw<<<1536, 256>>>(m0w, m1w, m2w);
    k_embed<<<NQ, 96>>>(qp);
    k_proj<<<SGRID / TILE, NTHR, SM_SMALL>>>(x, proj_w, proj_b);
    k_zero<<<2048, 256>>>();
    k_edges_mma<<<NEDGE / TM, ETHR, SMEM_E>>>(E, m0b, m1b, m2b);
    k_pred<<<NQ / TILE, NTHR, SM_SMALL>>>(p0w, p0b, p1w, p1b, out);
}

// round 8
// speedup vs baseline: 2.0997x; 2.0997x over previous
#include <cuda_runtime.h>
#include <cstdint>

typedef unsigned long long u64;

#define NQ 32768
#define SGRID 32768
#define NEDGE 262144
#define C 192
#define C2 384
#define IDXMASK 32767
#define TILE 64
#define NTHR 384
#define KT 32
#define SROW 66

// Scratch (device globals; no allocation allowed)
__device__ __align__(16) float g_qe[(size_t)NQ * C];
__device__ __align__(16) float g_u[(size_t)SGRID * C2];    // x @ Cw + cb
__device__ __align__(16) float g_v[(size_t)NQ * C2];       // qe @ W0_bot + b0
__device__ __align__(16) float g_seg[(size_t)NQ * C2];     // seg_sum of h1 (384-wide)
__device__ __align__(16) float g_cw[C * C2];               // proj_w @ W0_top
__device__ __align__(16) float g_cb[C2];                   // proj_b @ W0_top
__device__ int g_cnt[NQ];
__device__ int g_edge64;

// ---------- helpers ----------
__device__ __forceinline__ float gelu_f(float x) {
    return 0.5f * x * (1.0f + erff(x * 0.7071067811865476f));
}
__device__ __forceinline__ void load_edge(const void* Eg, int e, int& q, int& g) {
    if (g_edge64) {
        const long long* E = (const long long*)Eg;
        q = (int)E[2 * (size_t)e] & IDXMASK; g = (int)E[2 * (size_t)e + 1] & IDXMASK;
    } else {
        const int* E = (const int*)Eg;
        q = E[2 * (size_t)e] & IDXMASK; g = E[2 * (size_t)e + 1] & IDXMASK;
    }
}
__device__ __forceinline__ u64 pk2(float lo, float hi) { u64 r; asm("mov.b64 %0,{%1,%2};" : "=l"(r) : "f"(lo), "f"(hi)); return r; }
__device__ __forceinline__ void upk2(u64 v, float& lo, float& hi) { asm("mov.b64 {%0,%1},%2;" : "=f"(lo), "=f"(hi) : "l"(v)); }
__device__ __forceinline__ u64 fma2(u64 a, u64 b, u64 c) { u64 d; asm("fma.rn.f32x2 %0,%1,%2,%3;" : "=l"(d) : "l"(a), "l"(b), "l"(c)); return d; }

// One dense layer on a 64-sample tile in smem ([feature][sample] layout, stride SROW).
// W row-major [KIN][NTOT] in gmem. 384 threads.
template<int KIN, int NTOT, bool DOGELU>
__device__ __forceinline__ void layer_mlp(const float* __restrict__ Wg, const float* __restrict__ bg,
                                          const float* src, float* dst, float* wt, int tid)
{
    const int tx = tid % 48, ty = tid / 48;
    for (int nc = 0; nc < NTOT; nc += 192) {
        u64 acc[4][4];
        #pragma unroll
        for (int p = 0; p < 4; p++)
            #pragma unroll
            for (int ci = 0; ci < 4; ci++) acc[p][ci] = 0ull;
        for (int kt0 = 0; kt0 < KIN; kt0 += KT) {
            #pragma unroll
            for (int j = 0; j < 4; j++) {
                int f = tid + j * NTHR, r = f / 48, c4 = f % 48;
                float4 v = *(const float4*)&Wg[(size_t)(kt0 + r) * NTOT + nc + c4 * 4];
                *(float4*)&wt[r * 192 + c4 * 4] = v;
            }
            __syncthreads();
            #pragma unroll
            for (int kk = 0; kk < KT; kk++) {
                const float* srow = src + (kt0 + kk) * SROW + 8 * ty;
                u64 a0 = *(const u64*)&srow[0], a1 = *(const u64*)&srow[2];
                u64 a2 = *(const u64*)&srow[4], a3 = *(const u64*)&srow[6];
                float4 bv = *(const float4*)&wt[kk * 192 + tx * 4];
                u64 b0 = pk2(bv.x, bv.x), b1 = pk2(bv.y, bv.y), b2 = pk2(bv.z, bv.z), b3 = pk2(bv.w, bv.w);
                acc[0][0]=fma2(a0,b0,acc[0][0]); acc[0][1]=fma2(a0,b1,acc[0][1]); acc[0][2]=fma2(a0,b2,acc[0][2]); acc[0][3]=fma2(a0,b3,acc[0][3]);
                acc[1][0]=fma2(a1,b0,acc[1][0]); acc[1][1]=fma2(a1,b1,acc[1][1]); acc[1][2]=fma2(a1,b2,acc[1][2]); acc[1][3]=fma2(a1,b3,acc[1][3]);
                acc[2][0]=fma2(a2,b0,acc[2][0]); acc[2][1]=fma2(a2,b1,acc[2][1]); acc[2][2]=fma2(a2,b2,acc[2][2]); acc[2][3]=fma2(a2,b3,acc[2][3]);
                acc[3][0]=fma2(a3,b0,acc[3][0]); acc[3][1]=fma2(a3,b1,acc[3][1]); acc[3][2]=fma2(a3,b2,acc[3][2]); acc[3][3]=fma2(a3,b3,acc[3][3]);
            }
            __syncthreads();
        }
        #pragma unroll
        for (int ci = 0; ci < 4; ci++) {
            int col = nc + tx * 4 + ci;
            float bb = bg[col];
            #pragma unroll
            for (int p = 0; p < 4; p++) {
                float lo, hi; upk2(acc[p][ci], lo, hi);
                lo += bb; hi += bb;
                if (DOGELU) { lo = gelu_f(lo); hi = gelu_f(hi); }
                *(u64*)&dst[(size_t)col * SROW + 8 * ty + 2 * p] = pk2(lo, hi);
            }
        }
    }
}

// ---------- small kernels ----------
__global__ void k_detect(const int* __restrict__ E32) {
    if (threadIdx.x == 0) {
        int mode = 1;
        for (int i = 1; i < 128; i += 2) if (E32[i] != 0) { mode = 0; break; }
        g_edge64 = mode;
    }
}

__global__ void k_embed(const float* __restrict__ qp) {
    int q = blockIdx.x, t = threadIdx.x;
    int d = t >> 5, j = t & 31;
    float c = qp[q * 3 + d];
    float omega = powf(10000.0f, -(float)(2 * j) / 64.0f);
    float s, co; sincosf(c * omega, &s, &co);
    g_qe[(size_t)q * C + d * 64 + j]      = s;
    g_qe[(size_t)q * C + d * 64 + 32 + j] = co;
}

// Cw[i][n] = sum_j Pw[i][j] * W0[j][n] ; cb[n] = sum_j Pb[j] * W0[j][n]  (W0 rows 0..191)
__global__ void k_cw(const float* __restrict__ Pw, const float* __restrict__ Pb,
                     const float* __restrict__ W0) {
    __shared__ float row[C];
    int i = blockIdx.x, n = threadIdx.x;
    const float* src = (i < C) ? (Pw + (size_t)i * C) : Pb;
    for (int j = n; j < C; j += C2) row[j] = src[j];
    __syncthreads();
    float s = 0.0f;
    #pragma unroll 8
    for (int j = 0; j < C; j++) s += row[j] * W0[(size_t)j * C2 + n];
    if (i < C) g_cw[(size_t)i * C2 + n] = s;
    else       g_cb[n] = s;
}

__global__ void k_zero() {
    int idx = blockIdx.x * blockDim.x + threadIdx.x;
    int stride = gridDim.x * blockDim.x;
    for (int i = idx; i < NQ * C2; i += stride) g_seg[i] = 0.0f;
    for (int i = idx; i < NQ; i += stride) g_cnt[i] = 0;
}

// ---------- generic 192->384 tile GEMM body ----------
__device__ __forceinline__ void lin384_body(const float* __restrict__ src,
                                            const float* __restrict__ W,
                                            const float* __restrict__ bg,
                                            float* __restrict__ dst)
{
    extern __shared__ float sm[];
    float* bufA = sm;                    // [192][SROW]
    float* bufB = bufA + C * SROW;       // [384][SROW]
    float* wt   = bufB + C2 * SROW;      // KT*192
    int tid = threadIdx.x;
    int r0 = blockIdx.x * TILE;
    int e = tid / 6, t2 = tid % 6;
    {
        const float* s = src + (size_t)(r0 + e) * C + t2 * 32;
        int cbase = t2 * 32;
        #pragma unroll
        for (int i = 0; i < 8; i++) {
            float4 v = *(const float4*)(s + i * 4);
            int c = cbase + i * 4;
            bufA[(c+0)*SROW+e]=v.x; bufA[(c+1)*SROW+e]=v.y; bufA[(c+2)*SROW+e]=v.z; bufA[(c+3)*SROW+e]=v.w;
        }
    }
    __syncthreads();
    layer_mlp<C, C2, false>(W, bg, bufA, bufB, wt, tid);
    __syncthreads();
    {
        int cb = t2 * 64;
        float* drow = dst + (size_t)(r0 + e) * C2 + cb;
        #pragma unroll
        for (int i = 0; i < 16; i++) {
            float4 v;
            v.x = bufB[(size_t)(cb + i*4 + 0) * SROW + e];
            v.y = bufB[(size_t)(cb + i*4 + 1) * SROW + e];
            v.z = bufB[(size_t)(cb + i*4 + 2) * SROW + e];
            v.w = bufB[(size_t)(cb + i*4 + 3) * SROW + e];
            *(float4*)(drow + i * 4) = v;
        }
    }
}

__global__ void __launch_bounds__(NTHR, 1) k_ux(const float* __restrict__ x) {
    lin384_body(x, g_cw, g_cb, g_u);
}
__global__ void __launch_bounds__(NTHR, 1) k_vx(const float* __restrict__ m0w,
                                                const float* __restrict__ m0b) {
    lin384_body(g_qe, m0w + (size_t)C * C2, m0b, g_v);
}

// ---------- fused edge kernel: gelu(U[g]+V[q]) -> L1 GEMM+gelu -> 384-wide segment sum ----------
__global__ void __launch_bounds__(NTHR, 1) k_edges2(const void* __restrict__ Eg,
    const float* __restrict__ W1, const float* __restrict__ b1)
{
    extern __shared__ float sm[];
    float* bufA = sm;                     // [384][SROW]
    float* bufB = bufA + C2 * SROW;       // [384][SROW]
    float* wt   = bufB + C2 * SROW;       // KT*192
    int* qs = (int*)(wt + KT * 192);      // [64]
    int tid = threadIdx.x;
    int e0 = blockIdx.x * TILE;
    {
        int e = tid / 6, t2 = tid % 6;
        int q, g; load_edge(Eg, e0 + e, q, g);
        if (t2 == 0) qs[e] = q;
        const float4* up = (const float4*)(g_u + (size_t)g * C2 + t2 * 64);
        const float4* vp = (const float4*)(g_v + (size_t)q * C2 + t2 * 64);
        int kb = t2 * 64;
        #pragma unroll 4
        for (int i = 0; i < 16; i++) {
            float4 a = up[i], b = vp[i];
            int k = kb + i * 4;
            bufA[(k+0)*SROW+e] = gelu_f(a.x + b.x);
            bufA[(k+1)*SROW+e] = gelu_f(a.y + b.y);
            bufA[(k+2)*SROW+e] = gelu_f(a.z + b.z);
            bufA[(k+3)*SROW+e] = gelu_f(a.w + b.w);
        }
    }
    __syncthreads();
    layer_mlp<C2, C2, true>(W1, b1, bufA, bufB, wt, tid);
    __syncthreads();
    // segment-sum (sorted qidx -> contiguous runs); 384 threads = 384 columns
    {
        int c = tid;
        int cur = qs[0];
        float s = bufB[(size_t)c * SROW + 0];
        for (int e = 1; e < TILE; e++) {
            int q = qs[e];
            float v = bufB[(size_t)c * SROW + e];
            if (q == cur) s += v;
            else { atomicAdd(&g_seg[(size_t)cur * C2 + c], s); cur = q; s = v; }
        }
        atomicAdd(&g_seg[(size_t)cur * C2 + c], s);
    }
    if (tid == 0) {
        int cur = qs[0], n = 1;
        for (int e = 1; e < TILE; e++) {
            int q = qs[e];
            if (q == cur) n++;
            else { atomicAdd(&g_cnt[cur], n); cur = q; n = 1; }
        }
        atomicAdd(&g_cnt[cur], n);
    }
}

// ---------- per-query tail: m = (S@W2 + cnt*b2)/max(cnt,1) ; out = gelu(m@p0+b)@p1+b ----------
__global__ void __launch_bounds__(NTHR, 1) k_pred2(
    const float* __restrict__ W2, const float* __restrict__ b2,
    const float* __restrict__ p0w, const float* __restrict__ p0b,
    const float* __restrict__ p1w, const float* __restrict__ p1b,
    float* __restrict__ out)
{
    extern __shared__ float sm[];
    float* bufA = sm;                    // [384][SROW]
    float* bufB = bufA + C2 * SROW;      // [192][SROW]
    float* wt   = bufB + C * SROW;       // KT*192
    int* czero  = (int*)(wt + KT * 192); // [64]
    int tid = threadIdx.x;
    int q0 = blockIdx.x * TILE;
    {
        int e = tid / 6, t2 = tid % 6;
        int q = q0 + e;
        int cnt = g_cnt[q];
        float inv = 1.0f / fmaxf((float)cnt, 1.0f);
        if (t2 == 0) czero[e] = (cnt == 0);
        const float4* sp = (const float4*)(g_seg + (size_t)q * C2 + t2 * 64);
        int kb = t2 * 64;
        #pragma unroll
        for (int i = 0; i < 16; i++) {
            float4 v = sp[i];
            int k = kb + i * 4;
            bufA[(k+0)*SROW+e]=v.x*inv; bufA[(k+1)*SROW+e]=v.y*inv;
            bufA[(k+2)*SROW+e]=v.z*inv; bufA[(k+3)*SROW+e]=v.w*inv;
        }
    }
    __syncthreads();
    layer_mlp<C2, C, false>(W2, b2, bufA, bufB, wt, tid);
    __syncthreads();
    {   // zero rows with cnt==0 (reference: m = 0 there)
        int e = tid & 63, ch = tid / 64;   // 6 chunks x 32 cols
        if (czero[e]) {
            #pragma unroll
            for (int j = 0; j < 32; j++) bufB[(size_t)(ch * 32 + j) * SROW + e] = 0.0f;
        }
    }
    __syncthreads();
    layer_mlp<C, C, true>(p0w, p0b, bufB, bufA, wt, tid);
    __syncthreads();
    if (tid < 256) {
        int q = tid >> 2, o = tid & 3;
        float s = p1b[o];
        #pragma unroll 8
        for (int k = 0; k < C; k++)
            s += bufA[(size_t)k * SROW + q] * p1w[k * 4 + o];
        out[(size_t)(q0 + q) * 4 + o] = s;
    }
}

extern "C" void kernel_launch(void* const* d_in, const int* in_sizes, int n_in,
                              void* d_out, int out_size)
{
    const float* x      = (const float*)d_in[0];
    const float* qp     = (const float*)d_in[1];
    const void*  E      = d_in[2];
    const float* proj_w = (const float*)d_in[3];
    const float* proj_b = (const float*)d_in[4];
    const float* m0w    = (const float*)d_in[5];
    const float* m0b    = (const float*)d_in[6];
    const float* m1w    = (const float*)d_in[7];
    const float* m1b    = (const float*)d_in[8];
    const float* m2w    = (const float*)d_in[9];
    const float* m2b    = (const float*)d_in[10];
    const float* p0w    = (const float*)d_in[11];
    const float* p0b    = (const float*)d_in[12];
    const float* p1w    = (const float*)d_in[13];
    const float* p1b    = (const float*)d_in[14];
    float* out = (float*)d_out;

    const int SM_LIN  = (C * SROW + C2 * SROW + KT * 192) * 4;            // 176,640
    const int SM_EDGE = (2 * C2 * SROW + KT * 192) * 4 + TILE * 4;        // 227,584
    const int SM_PRED = (C2 * SROW + C * SROW + KT * 192) * 4 + TILE * 4; // 176,896

    cudaFuncSetAttribute(k_ux,     cudaFuncAttributeMaxDynamicSharedMemorySize, SM_LIN);
    cudaFuncSetAttribute(k_vx,     cudaFuncAttributeMaxDynamicSharedMemorySize, SM_LIN);
    cudaFuncSetAttribute(k_edges2, cudaFuncAttributeMaxDynamicSharedMemorySize, SM_EDGE);
    cudaFuncSetAttribute(k_pred2,  cudaFuncAttributeMaxDynamicSharedMemorySize, SM_PRED);

    k_detect<<<1, 32>>>((const int*)E);
    k_embed<<<NQ, 96>>>(qp);
    k_cw<<<C + 1, C2>>>(proj_w, proj_b, m0w);
    k_ux<<<SGRID / TILE, NTHR, SM_LIN>>>(x);
    k_vx<<<NQ / TILE, NTHR, SM_LIN>>>(m0w, m0b);
    k_zero<<<2048, 256>>>();
    k_edges2<<<NEDGE / TILE, NTHR, SM_EDGE>>>(E, m1w, m1b);
    k_pred2<<<NQ / TILE, NTHR, SM_PRED>>>(m2w, m2b, p0w, p0b, p1w, p1b, out);
}

// round 9
// speedup vs baseline: 2.2145x; 1.0547x over previous
#include <cuda_runtime.h>
#include <cstdint>

typedef unsigned long long u64;

#define NQ 32768
#define SGRID 32768
#define NEDGE 262144
#define C 192
#define C2 384
#define IDXMASK 32767
#define TILE 64
#define NTHR 384
#define KT 24
#define SROW 68   // floats; 272 B row stride (16B aligned for LDS.128)

// Scratch (device globals; no allocation allowed)
__device__ __align__(16) float g_qe[(size_t)NQ * C];
__device__ __align__(16) float g_u[(size_t)SGRID * C2];    // x @ Cw + cb
__device__ __align__(16) float g_v[(size_t)NQ * C2];       // qe @ W0_bot + b0
__device__ __align__(16) float g_seg[(size_t)NQ * C2];     // seg_sum of h1 (384-wide)
__device__ __align__(16) float g_cw[C * C2];               // proj_w @ W0_top
__device__ __align__(16) float g_cb[C2];                   // proj_b @ W0_top
__device__ int g_cnt[NQ];
__device__ int g_edge64;

// ---------- helpers ----------
__device__ __forceinline__ float gelu_f(float x) {
    return 0.5f * x * (1.0f + erff(x * 0.7071067811865476f));
}
__device__ __forceinline__ void load_edge(const void* Eg, int e, int& q, int& g) {
    if (g_edge64) {
        const long long* E = (const long long*)Eg;
        q = (int)E[2 * (size_t)e] & IDXMASK; g = (int)E[2 * (size_t)e + 1] & IDXMASK;
    } else {
        const int* E = (const int*)Eg;
        q = E[2 * (size_t)e] & IDXMASK; g = E[2 * (size_t)e + 1] & IDXMASK;
    }
}
__device__ __forceinline__ u64 pk2(float lo, float hi) { u64 r; asm("mov.b64 %0,{%1,%2};" : "=l"(r) : "f"(lo), "f"(hi)); return r; }
__device__ __forceinline__ void upk2(u64 v, float& lo, float& hi) { asm("mov.b64 {%0,%1},%2;" : "=f"(lo), "=f"(hi) : "l"(v)); }
__device__ __forceinline__ u64 fma2(u64 a, u64 b, u64 c) { u64 d; asm("fma.rn.f32x2 %0,%1,%2,%3;" : "=l"(d) : "l"(a), "l"(b), "l"(c)); return d; }

// One dense layer on a 64-sample tile in smem ([feature][sample] layout, stride SROW).
// W row-major [KIN][NTOT] in gmem. 384 threads. W staging is double-buffered
// through registers: next k-block's LDGs issue right after the barrier and
// retire under the 24 k-steps of FMA work.
template<int KIN, int NTOT, bool DOGELU>
__device__ __forceinline__ void layer_mlp(const float* __restrict__ Wg, const float* __restrict__ bg,
                                          const float* src, float* dst, float* wt, int tid)
{
    const int tx = tid % 48, ty = tid / 48;
    int rs[3], cs[3];
    #pragma unroll
    for (int j = 0; j < 3; j++) { int f = tid + j * NTHR; rs[j] = f / 48; cs[j] = (f % 48) * 4; }

    for (int nc = 0; nc < NTOT; nc += 192) {
        u64 acc[4][4];
        #pragma unroll
        for (int p = 0; p < 4; p++)
            #pragma unroll
            for (int ci = 0; ci < 4; ci++) acc[p][ci] = 0ull;

        float4 pf[3];
        #pragma unroll
        for (int j = 0; j < 3; j++)
            pf[j] = *(const float4*)&Wg[(size_t)rs[j] * NTOT + nc + cs[j]];

        for (int kt0 = 0; kt0 < KIN; kt0 += KT) {
            #pragma unroll
            for (int j = 0; j < 3; j++)
                *(float4*)&wt[rs[j] * 192 + cs[j]] = pf[j];
            __syncthreads();
            if (kt0 + KT < KIN) {
                #pragma unroll
                for (int j = 0; j < 3; j++)
                    pf[j] = *(const float4*)&Wg[(size_t)(kt0 + KT + rs[j]) * NTOT + nc + cs[j]];
            }
            #pragma unroll
            for (int kk = 0; kk < KT; kk++) {
                const float* srow = src + (kt0 + kk) * SROW + 8 * ty;
                ulonglong2 aA = *(const ulonglong2*)srow;
                ulonglong2 aB = *(const ulonglong2*)(srow + 4);
                u64 a0 = aA.x, a1 = aA.y, a2 = aB.x, a3 = aB.y;
                float4 bv = *(const float4*)&wt[kk * 192 + tx * 4];
                u64 b0 = pk2(bv.x, bv.x), b1 = pk2(bv.y, bv.y), b2 = pk2(bv.z, bv.z), b3 = pk2(bv.w, bv.w);
                acc[0][0]=fma2(a0,b0,acc[0][0]); acc[0][1]=fma2(a0,b1,acc[0][1]); acc[0][2]=fma2(a0,b2,acc[0][2]); acc[0][3]=fma2(a0,b3,acc[0][3]);
                acc[1][0]=fma2(a1,b0,acc[1][0]); acc[1][1]=fma2(a1,b1,acc[1][1]); acc[1][2]=fma2(a1,b2,acc[1][2]); acc[1][3]=fma2(a1,b3,acc[1][3]);
                acc[2][0]=fma2(a2,b0,acc[2][0]); acc[2][1]=fma2(a2,b1,acc[2][1]); acc[2][2]=fma2(a2,b2,acc[2][2]); acc[2][3]=fma2(a2,b3,acc[2][3]);
                acc[3][0]=fma2(a3,b0,acc[3][0]); acc[3][1]=fma2(a3,b1,acc[3][1]); acc[3][2]=fma2(a3,b2,acc[3][2]); acc[3][3]=fma2(a3,b3,acc[3][3]);
            }
            __syncthreads();
        }
        #pragma unroll
        for (int ci = 0; ci < 4; ci++) {
            int col = nc + tx * 4 + ci;
            float bb = bg[col];
            u64 st[4];
            #pragma unroll
            for (int p = 0; p < 4; p++) {
                float lo, hi; upk2(acc[p][ci], lo, hi);
                lo += bb; hi += bb;
                if (DOGELU) { lo = gelu_f(lo); hi = gelu_f(hi); }
                st[p] = pk2(lo, hi);
            }
            ulonglong2* dp = (ulonglong2*)&dst[(size_t)col * SROW + 8 * ty];
            dp[0] = make_ulonglong2(st[0], st[1]);
            dp[1] = make_ulonglong2(st[2], st[3]);
        }
    }
}

// ---------- small kernels ----------
__global__ void k_detect(const int* __restrict__ E32) {
    if (threadIdx.x == 0) {
        int mode = 1;
        for (int i = 1; i < 128; i += 2) if (E32[i] != 0) { mode = 0; break; }
        g_edge64 = mode;
    }
}

__global__ void k_embed(const float* __restrict__ qp) {
    int q = blockIdx.x, t = threadIdx.x;
    int d = t >> 5, j = t & 31;
    float c = qp[q * 3 + d];
    float omega = powf(10000.0f, -(float)(2 * j) / 64.0f);
    float s, co; sincosf(c * omega, &s, &co);
    g_qe[(size_t)q * C + d * 64 + j]      = s;
    g_qe[(size_t)q * C + d * 64 + 32 + j] = co;
}

// Cw[i][n] = sum_j Pw[i][j] * W0[j][n] ; cb[n] = sum_j Pb[j] * W0[j][n]
__global__ void k_cw(const float* __restrict__ Pw, const float* __restrict__ Pb,
                     const float* __restrict__ W0) {
    __shared__ float row[C];
    int i = blockIdx.x, n = threadIdx.x;
    const float* src = (i < C) ? (Pw + (size_t)i * C) : Pb;
    for (int j = n; j < C; j += C2) row[j] = src[j];
    __syncthreads();
    float s = 0.0f;
    #pragma unroll 8
    for (int j = 0; j < C; j++) s += row[j] * W0[(size_t)j * C2 + n];
    if (i < C) g_cw[(size_t)i * C2 + n] = s;
    else       g_cb[n] = s;
}

__global__ void k_zero() {
    int idx = blockIdx.x * blockDim.x + threadIdx.x;
    int stride = gridDim.x * blockDim.x;
    for (int i = idx; i < NQ * C2; i += stride) g_seg[i] = 0.0f;
    for (int i = idx; i < NQ; i += stride) g_cnt[i] = 0;
}

// ---------- generic 192->384 tile GEMM body ----------
__device__ __forceinline__ void lin384_body(const float* __restrict__ src,
                                            const float* __restrict__ W,
                                            const float* __restrict__ bg,
                                            float* __restrict__ dst)
{
    extern __shared__ float sm[];
    float* bufA = sm;                    // [192][SROW]
    float* bufB = bufA + C * SROW;       // [384][SROW]
    float* wt   = bufB + C2 * SROW;      // KT*192
    int tid = threadIdx.x;
    int r0 = blockIdx.x * TILE;
    int e = tid / 6, t2 = tid % 6;
    {
        const float* s = src + (size_t)(r0 + e) * C + t2 * 32;
        int cbase = t2 * 32;
        #pragma unroll
        for (int i = 0; i < 8; i++) {
            float4 v = *(const float4*)(s + i * 4);
            int c = cbase + i * 4;
            bufA[(c+0)*SROW+e]=v.x; bufA[(c+1)*SROW+e]=v.y; bufA[(c+2)*SROW+e]=v.z; bufA[(c+3)*SROW+e]=v.w;
        }
    }
    __syncthreads();
    layer_mlp<C, C2, false>(W, bg, bufA, bufB, wt, tid);
    __syncthreads();
    {
        int cb = t2 * 64;
        float* drow = dst + (size_t)(r0 + e) * C2 + cb;
        #pragma unroll
        for (int i = 0; i < 16; i++) {
            float4 v;
            v.x = bufB[(size_t)(cb + i*4 + 0) * SROW + e];
            v.y = bufB[(size_t)(cb + i*4 + 1) * SROW + e];
            v.z = bufB[(size_t)(cb + i*4 + 2) * SROW + e];
            v.w = bufB[(size_t)(cb + i*4 + 3) * SROW + e];
            *(float4*)(drow + i * 4) = v;
        }
    }
}

__global__ void __launch_bounds__(NTHR, 1) k_ux(const float* __restrict__ x) {
    lin384_body(x, g_cw, g_cb, g_u);
}
__global__ void __launch_bounds__(NTHR, 1) k_vx(const float* __restrict__ m0w,
                                                const float* __restrict__ m0b) {
    lin384_body(g_qe, m0w + (size_t)C * C2, m0b, g_v);
}

// ---------- fused edge kernel: gelu(U[g]+V[q]) -> L1 GEMM+gelu -> 384-wide segment sum ----------
__global__ void __launch_bounds__(NTHR, 1) k_edges2(const void* __restrict__ Eg,
    const float* __restrict__ W1, const float* __restrict__ b1)
{
    extern __shared__ float sm[];
    float* bufA = sm;                     // [384][SROW]
    float* bufB = bufA + C2 * SROW;       // [384][SROW]
    float* wt   = bufB + C2 * SROW;       // KT*192
    int* qs = (int*)(wt + KT * 192);      // [64]
    int tid = threadIdx.x;
    int e0 = blockIdx.x * TILE;
    {
        int e = tid / 6, t2 = tid % 6;
        int q, g; load_edge(Eg, e0 + e, q, g);
        if (t2 == 0) qs[e] = q;
        const float4* up = (const float4*)(g_u + (size_t)g * C2 + t2 * 64);
        const float4* vp = (const float4*)(g_v + (size_t)q * C2 + t2 * 64);
        int kb = t2 * 64;
        #pragma unroll 4
        for (int i = 0; i < 16; i++) {
            float4 a = up[i], b = vp[i];
            int k = kb + i * 4;
            bufA[(k+0)*SROW+e] = gelu_f(a.x + b.x);
            bufA[(k+1)*SROW+e] = gelu_f(a.y + b.y);
            bufA[(k+2)*SROW+e] = gelu_f(a.z + b.z);
            bufA[(k+3)*SROW+e] = gelu_f(a.w + b.w);
        }
    }
    __syncthreads();
    layer_mlp<C2, C2, true>(W1, b1, bufA, bufB, wt, tid);
    __syncthreads();
    // segment-sum (sorted qidx -> contiguous runs); 384 threads = 384 columns
    {
        int c = tid;
        int cur = qs[0];
        float s = bufB[(size_t)c * SROW + 0];
        for (int e = 1; e < TILE; e++) {
            int q = qs[e];
            float v = bufB[(size_t)c * SROW + e];
            if (q == cur) s += v;
            else { atomicAdd(&g_seg[(size_t)cur * C2 + c], s); cur = q; s = v; }
        }
        atomicAdd(&g_seg[(size_t)cur * C2 + c], s);
    }
    if (tid == 0) {
        int cur = qs[0], n = 1;
        for (int e = 1; e < TILE; e++) {
            int q = qs[e];
            if (q == cur) n++;
            else { atomicAdd(&g_cnt[cur], n); cur = q; n = 1; }
        }
        atomicAdd(&g_cnt[cur], n);
    }
}

// ---------- per-query tail: m = (S@W2)/cnt + b2 (cnt>0) ; out = gelu(m@p0+b)@p1+b ----------
__global__ void __launch_bounds__(NTHR, 1) k_pred2(
    const float* __restrict__ W2, const float* __restrict__ b2,
    const float* __restrict__ p0w, const float* __restrict__ p0b,
    const float* __restrict__ p1w, const float* __restrict__ p1b,
    float* __restrict__ out)
{
    extern __shared__ float sm[];
    float* bufA = sm;                    // [384][SROW]
    float* bufB = bufA + C2 * SROW;      // [192][SROW]
    float* wt   = bufB + C * SROW;       // KT*192
    int* czero  = (int*)(wt + KT * 192); // [64]
    int tid = threadIdx.x;
    int q0 = blockIdx.x * TILE;
    {
        int e = tid / 6, t2 = tid % 6;
        int q = q0 + e;
        int cnt = g_cnt[q];
        float inv = 1.0f / fmaxf((float)cnt, 1.0f);
        if (t2 == 0) czero[e] = (cnt == 0);
        const float4* sp = (const float4*)(g_seg + (size_t)q * C2 + t2 * 64);
        int kb = t2 * 64;
        #pragma unroll
        for (int i = 0; i < 16; i++) {
            float4 v = sp[i];
            int k = kb + i * 4;
            bufA[(k+0)*SROW+e]=v.x*inv; bufA[(k+1)*SROW+e]=v.y*inv;
            bufA[(k+2)*SROW+e]=v.z*inv; bufA[(k+3)*SROW+e]=v.w*inv;
        }
    }
    __syncthreads();
    layer_mlp<C2, C, false>(W2, b2, bufA, bufB, wt, tid);
    __syncthreads();
    {   // zero rows with cnt==0 (reference: m = 0 there)
        int e = tid & 63, ch = tid / 64;   // 6 chunks x 32 cols
        if (czero[e]) {
            #pragma unroll
            for (int j = 0; j < 32; j++) bufB[(size_t)(ch * 32 + j) * SROW + e] = 0.0f;
        }
    }
    __syncthreads();
    layer_mlp<C, C, true>(p0w, p0b, bufB, bufA, wt, tid);
    __syncthreads();
    if (tid < 256) {
        int q = tid >> 2, o = tid & 3;
        float s = p1b[o];
        #pragma unroll 8
        for (int k = 0; k < C; k++)
            s += bufA[(size_t)k * SROW + q] * p1w[k * 4 + o];
        out[(size_t)(q0 + q) * 4 + o] = s;
    }
}

extern "C" void kernel_launch(void* const* d_in, const int* in_sizes, int n_in,
                              void* d_out, int out_size)
{
    const float* x      = (const float*)d_in[0];
    const float* qp     = (const float*)d_in[1];
    const void*  E      = d_in[2];
    const float* proj_w = (const float*)d_in[3];
    const float* proj_b = (const float*)d_in[4];
    const float* m0w    = (const float*)d_in[5];
    const float* m0b    = (const float*)d_in[6];
    const float* m1w    = (const float*)d_in[7];
    const float* m1b    = (const float*)d_in[8];
    const float* m2w    = (const float*)d_in[9];
    const float* m2b    = (const float*)d_in[10];
    const float* p0w    = (const float*)d_in[11];
    const float* p0b    = (const float*)d_in[12];
    const float* p1w    = (const float*)d_in[13];
    const float* p1b    = (const float*)d_in[14];
    float* out = (float*)d_out;

    const int SM_LIN  = (C * SROW + C2 * SROW + KT * 192) * 4;            // 175,104
    const int SM_EDGE = (2 * C2 * SROW + KT * 192) * 4 + TILE * 4;        // 227,584
    const int SM_PRED = (C2 * SROW + C * SROW + KT * 192) * 4 + TILE * 4; // 175,360

    cudaFuncSetAttribute(k_ux,     cudaFuncAttributeMaxDynamicSharedMemorySize, SM_LIN);
    cudaFuncSetAttribute(k_vx,     cudaFuncAttributeMaxDynamicSharedMemorySize, SM_LIN);
    cudaFuncSetAttribute(k_edges2, cudaFuncAttributeMaxDynamicSharedMemorySize, SM_EDGE);
    cudaFuncSetAttribute(k_pred2,  cudaFuncAttributeMaxDynamicSharedMemorySize, SM_PRED);

    k_detect<<<1, 32>>>((const int*)E);
    k_embed<<<NQ, 96>>>(qp);
    k_cw<<<C + 1, C2>>>(proj_w, proj_b, m0w);
    k_ux<<<SGRID / TILE, NTHR, SM_LIN>>>(x);
    k_vx<<<NQ / TILE, NTHR, SM_LIN>>>(m0w, m0b);
    k_zero<<<2048, 256>>>();
    k_edges2<<<NEDGE / TILE, NTHR, SM_EDGE>>>(E, m1w, m1b);
    k_pred2<<<NQ / TILE, NTHR, SM_PRED>>>(m2w, m2b, p0w, p0b, p1w, p1b, out);
}